// round 14
// baseline (speedup 1.0000x reference)
#include <cuda_runtime.h>
#include <cuda_bf16.h>
#include <math.h>
#include <stdint.h>

#define Bc 8
#define Sc 32
#define Dc 256
#define Nc 256
#define Kc 51
#define EMAX 1024
#define VMAX 50432

// ---------------- scratch ----------------
__device__ float g_x[Sc * Bc * Dc];
__device__ float g_scores[Sc * Bc * Nc];
__device__ float g_w[Sc * Bc * Kc];
__device__ int   g_active[Sc * Kc];
__device__ int   g_gecnt;
__device__ int   g_pcnt;
__device__ int   g_glist[Sc * EMAX];
__device__ int   g_gdst[Sc * EMAX];
__device__ int   g_gsorted[Sc * EMAX];
__device__ int   g_pairA[Sc * EMAX];
__device__ int   g_pairB[Sc * EMAX];
__device__ int   g_pairD[Sc * EMAX];
__device__ int   g_eid[Sc * EMAX];
__device__ int   g_eps[Sc * EMAX];
__device__ int   g_epd[Sc * EMAX];
__device__ int   g_ncnt[Nc];
__device__ int   g_nlist[Nc * Sc];
__device__ float g_states[Sc * Kc * Bc * Dc];
__device__ float g_nxt[Sc * Kc * Bc * Dc];
__device__ __align__(16) __nv_bfloat16 g_Ah[256 * 256];
__device__ __align__(16) __nv_bfloat16 g_Al[256 * 256];
__device__ __align__(16) __nv_bfloat16 g_xh[Sc * Bc * Dc];
__device__ __align__(16) __nv_bfloat16 g_xl[Sc * Bc * Dc];
__device__ __align__(16) __nv_bfloat16 g_fch[Nc * Dc * Dc];
__device__ __align__(16) __nv_bfloat16 g_fcl[Nc * Dc * Dc];
__device__ __align__(16) __nv_bfloat16 g_oWh[VMAX * Dc];
__device__ __align__(16) __nv_bfloat16 g_oWl[VMAX * Dc];

// ---------------- helpers ----------------
__device__ __forceinline__ float gelu_exact(float x) {
    return 0.5f * x * (1.0f + erff(x * 0.70710678118654752440f));
}
__device__ __forceinline__ float sigmoidf_(float x) {
    return 1.0f / (1.0f + expf(-x));
}
__device__ __forceinline__ unsigned long long ullmax_(unsigned long long a, unsigned long long b) {
    return a > b ? a : b;
}
__device__ __forceinline__ uint32_t smem_u32(const void* p) {
    uint32_t a;
    asm("{ .reg .u64 t; cvta.to.shared.u64 t, %1; cvt.u32.u64 %0, t; }" : "=r"(a) : "l"(p));
    return a;
}
__device__ __forceinline__ uint32_t sw128(uint32_t o) { return o ^ ((o >> 3) & 0x70); }

#define CP16(saddr, gptr) \
    asm volatile("cp.async.ca.shared.global [%0], [%1], 16;" :: "r"(saddr), "l"(gptr))
#define CPCOMMIT() asm volatile("cp.async.commit_group;")
#define CPWAIT() asm volatile("cp.async.wait_group 0;" ::: "memory")
#define CPWAIT1() asm volatile("cp.async.wait_group 1;" ::: "memory")

__device__ __forceinline__ void packpair(float a, float b, uint32_t& h, uint32_t& l) {
    uint32_t ua = __float_as_uint(a), ub = __float_as_uint(b);
    asm("prmt.b32 %0, %1, %2, 0x7632;" : "=r"(h) : "r"(ua), "r"(ub));
    float la = a - __uint_as_float(ua & 0xFFFF0000u);
    float lb = b - __uint_as_float(ub & 0xFFFF0000u);
    uint32_t ula = __float_as_uint(la), ulb = __float_as_uint(lb);
    asm("prmt.b32 %0, %1, %2, 0x7632;" : "=r"(l) : "r"(ula), "r"(ulb));
}
__device__ __forceinline__ void split1(float a, __nv_bfloat16& h, __nv_bfloat16& l) {
    uint32_t ua = __float_as_uint(a);
    uint16_t hb = (uint16_t)(ua >> 16);
    float lo = a - __uint_as_float(ua & 0xFFFF0000u);
    uint16_t lb = (uint16_t)(__float_as_uint(lo) >> 16);
    h = *(__nv_bfloat16*)&hb;
    l = *(__nv_bfloat16*)&lb;
}

__device__ __forceinline__ void ldsm_x4(uint32_t* r, uint32_t addr) {
    asm volatile("ldmatrix.sync.aligned.m8n8.x4.shared.b16 {%0,%1,%2,%3}, [%4];"
                 : "=r"(r[0]), "=r"(r[1]), "=r"(r[2]), "=r"(r[3]) : "r"(addr));
}
__device__ __forceinline__ void ldsm_x2(uint32_t* r, uint32_t addr) {
    asm volatile("ldmatrix.sync.aligned.m8n8.x2.shared.b16 {%0,%1}, [%2];"
                 : "=r"(r[0]), "=r"(r[1]) : "r"(addr));
}
__device__ __forceinline__ void mma_bf16(float* d, const uint32_t* a, const uint32_t* b) {
    asm volatile(
        "mma.sync.aligned.m16n8k16.row.col.f32.bf16.bf16.f32 "
        "{%0,%1,%2,%3}, {%4,%5,%6,%7}, {%8,%9}, {%0,%1,%2,%3};"
        : "+f"(d[0]), "+f"(d[1]), "+f"(d[2]), "+f"(d[3])
        : "r"(a[0]), "r"(a[1]), "r"(a[2]), "r"(a[3]), "r"(b[0]), "r"(b[1]));
}
__device__ __forceinline__ void mma_tf32f(float* d, uint32_t a0, uint32_t a1,
                                          uint32_t a2, uint32_t a3,
                                          uint32_t b0, uint32_t b1) {
    asm volatile(
        "mma.sync.aligned.m16n8k8.row.col.f32.tf32.tf32.f32 "
        "{%0,%1,%2,%3}, {%4,%5,%6,%7}, {%8,%9}, {%0,%1,%2,%3};"
        : "+f"(d[0]), "+f"(d[1]), "+f"(d[2]), "+f"(d[3])
        : "r"(a0), "r"(a1), "r"(a2), "r"(a3), "r"(b0), "r"(b1));
}

// ---------------- weight converters ----------------
__global__ void convert_fc_kernel(const float* __restrict__ fcW) {
    size_t i = ((size_t)blockIdx.x * 256 + threadIdx.x) * 8;
    const float4* s4 = (const float4*)(fcW + i);
    float4 w0 = s4[0], w1 = s4[1];
    uint4 h, l;
    packpair(w0.x, w0.y, h.x, l.x);
    packpair(w0.z, w0.w, h.y, l.y);
    packpair(w1.x, w1.y, h.z, l.z);
    packpair(w1.z, w1.w, h.w, l.w);
    *(uint4*)&g_fch[i] = h;
    *(uint4*)&g_fcl[i] = l;
}
__global__ void convert_ow_kernel(const float* __restrict__ oW, int V) {
    size_t i = ((size_t)blockIdx.x * 256 + threadIdx.x) * 8;
    if (i >= (size_t)V * Dc || i >= (size_t)VMAX * Dc) return;
    const float4* s4 = (const float4*)(oW + i);
    float4 w0 = s4[0], w1 = s4[1];
    uint4 h, l;
    packpair(w0.x, w0.y, h.x, l.x);
    packpair(w0.z, w0.w, h.y, l.y);
    packpair(w1.x, w1.y, h.z, l.z);
    packpair(w1.z, w1.w, h.w, l.w);
    *(uint4*)&g_oWh[i] = h;
    *(uint4*)&g_oWl[i] = l;
}

// ---------------- K1: embed ----------------
__global__ void embed_kernel(const int* __restrict__ ids,
                             const float* __restrict__ embed,
                             const float* __restrict__ pos) {
    int s = blockIdx.x / Bc, b = blockIdx.x % Bc, d = threadIdx.x;
    int id = ids[b * Sc + s];
    float v = embed[(size_t)id * Dc + d] + pos[s * Dc + d];
    int idx = (s * Bc + b) * Dc + d;
    g_x[idx] = v;
    __nv_bfloat16 h, l;
    split1(v, h, l);
    g_xh[idx] = h;
    g_xl[idx] = l;
}

// ---------------- K2: router ----------------
__global__ void __launch_bounds__(256) router_kernel(const float* __restrict__ rW,
                                                     const float* __restrict__ rb) {
    __shared__ float xs[Bc][Dc];
    int s = blockIdx.x;
    int t = threadIdx.x;
    for (int i = t; i < Bc * Dc; i += 256) xs[i >> 8][i & 255] = g_x[s * Bc * Dc + i];
    __syncthreads();
    int neuron = blockIdx.y * 64 + (t >> 2), part = t & 3;
    const float4* w4 = (const float4*)(rW + (size_t)neuron * Dc + part * 64);
    float acc[Bc];
#pragma unroll
    for (int b = 0; b < Bc; b++) acc[b] = 0.f;
#pragma unroll
    for (int q = 0; q < 16; q++) {
        float4 w = w4[q];
#pragma unroll
        for (int b = 0; b < Bc; b++) {
            float4 xv = *(const float4*)&xs[b][part * 64 + 4 * q];
            acc[b] += w.x * xv.x + w.y * xv.y + w.z * xv.z + w.w * xv.w;
        }
    }
#pragma unroll
    for (int o = 1; o <= 2; o <<= 1)
#pragma unroll
        for (int b = 0; b < Bc; b++) acc[b] += __shfl_xor_sync(0xffffffffu, acc[b], o);
    if (part == 0) {
        float bias = rb[neuron];
#pragma unroll
        for (int b = 0; b < Bc; b++) g_scores[(s * Bc + b) * Nc + neuron] = acc[b] + bias;
    }
}

// ---------------- K3: top-K ----------------
__global__ void topk_kernel() {
    int wid = threadIdx.x >> 5, lane = threadIdx.x & 31;
    int row = blockIdx.x * 4 + wid;
    int s = row / Bc, b = row % Bc;
    const float* sc = g_scores + row * Nc;

    unsigned long long key[Nc / 32];
#pragma unroll
    for (int j = 0; j < Nc / 32; j++) {
        int idx = j * 32 + lane;
        unsigned bits = __float_as_uint(sc[idx]);
        unsigned u = (bits & 0x80000000u) ? ~bits : (bits | 0x80000000u);
        key[j] = ((unsigned long long)u << 32) | (unsigned)(Nc - 1 - idx);
    }
    __shared__ float vals[4][Kc];
    for (int k = 0; k < Kc; k++) {
        unsigned long long m = key[0];
#pragma unroll
        for (int j = 1; j < Nc / 32; j++) m = ullmax_(m, key[j]);
        for (int o = 16; o; o >>= 1) m = ullmax_(m, __shfl_xor_sync(0xffffffffu, m, o));
        int idx = Nc - 1 - (int)(unsigned)(m & 0xffffffffu);
        if ((idx & 31) == lane) key[idx >> 5] = 0ull;
        unsigned u = (unsigned)(m >> 32);
        unsigned bits = (u & 0x80000000u) ? (u ^ 0x80000000u) : ~u;
        if (lane == 0) {
            vals[wid][k] = __uint_as_float(bits);
            if (b == 0) g_active[s * Kc + k] = idx;
        }
    }
    __syncwarp();
    float v0 = vals[wid][0];
    float e1 = (lane < Kc) ? expf(vals[wid][lane] - v0) : 0.f;
    float e2 = (lane + 32 < Kc) ? expf(vals[wid][lane + 32] - v0) : 0.f;
    float ssum = e1 + e2;
    for (int o = 16; o; o >>= 1) ssum += __shfl_xor_sync(0xffffffffu, ssum, o);
    float inv = 1.0f / ssum;
    if (lane < Kc) g_w[row * Kc + lane] = e1 * inv;
    if (lane + 32 < Kc) g_w[row * Kc + lane + 32] = e2 * inv;
}

// ---------------- K3b: group hop0 instances by neuron; zero global edge count ----
__global__ void build_groups_kernel() {
    int a = blockIdx.x;
    if (a == 0 && threadIdx.x == 0) g_gecnt = 0;
    __shared__ int cnt;
    if (threadIdx.x == 0) cnt = 0;
    __syncthreads();
    for (int i = threadIdx.x; i < Sc * Kc; i += blockDim.x) {
        if (g_active[i] == a) {
            int s = i / Kc, k = i - s * Kc;
            int slot = atomicAdd(&cnt, 1);
            g_nlist[a * Sc + slot] = (s << 8) | k;
        }
    }
    __syncthreads();
    if (threadIdx.x == 0) g_ncnt[a] = cnt;
}

// ---------------- K5: compact active edges (pos computed in smem) ----------------
__global__ void __launch_bounds__(256) efilter_kernel(const int* __restrict__ esrc,
                                                      const int* __restrict__ edst, int E) {
    __shared__ int pos[Nc];
    __shared__ int cnt;
    int s = blockIdx.x, t = threadIdx.x;
    pos[t] = -1;
    if (t == 0) cnt = 0;
    __syncthreads();
    if (t < Kc) pos[g_active[s * Kc + t]] = t;
    __syncthreads();
    for (int e = t; e < E; e += 256) {
        int ps = pos[esrc[e]];
        int pd = pos[edst[e]];
        if (ps >= 0 && pd >= 0) {
            int slot = atomicAdd(&cnt, 1);
            int code = s * EMAX + slot;
            g_eid[code] = e;
            g_eps[code] = ps;
            g_epd[code] = pd;
            int g = atomicAdd(&g_gecnt, 1);
            g_glist[g] = code;
            g_gdst[g] = edst[e];
        }
    }
}

// ---------------- K5b: counting sort by dst + build pairs ----------------
__global__ void __launch_bounds__(256) sort_pairs_kernel() {
    __shared__ int hist[Nc];
    __shared__ int base[Nc];
    __shared__ int cur[Nc];
    int t = threadIdx.x;
    int total = g_gecnt;
    hist[t] = 0;
    if (t == 0) g_pcnt = 0;
    __syncthreads();
    for (int i = t; i < total; i += 256) atomicAdd(&hist[g_gdst[i]], 1);
    __syncthreads();
    if (t == 0) {
        int acc = 0;
        for (int i = 0; i < Nc; i++) { base[i] = acc; acc += hist[i]; }
    }
    __syncthreads();
    cur[t] = base[t];
    __syncthreads();
    for (int i = t; i < total; i += 256) {
        int d = g_gdst[i];
        int p = atomicAdd(&cur[d], 1);
        g_gsorted[p] = g_glist[i];
    }
    __syncthreads();
    int start = base[t], cnt = hist[t];
    for (int i = 0; i < cnt; i += 2) {
        int slot = atomicAdd(&g_pcnt, 1);
        g_pairA[slot] = g_gsorted[start + i];
        g_pairB[slot] = (i + 1 < cnt) ? g_gsorted[start + i + 1] : -1;
        g_pairD[slot] = t;
    }
}

// ======== HMMA small-M tile machinery (hop0) ========
#define T_WH 0
#define T_WL 32768
#define T_AH 65536
#define T_AL 67584
#define T_GATE 69632
#define H_SMEM (69632 + 64)

__device__ __forceinline__ void mma_chunk(float acc[4][4], uint32_t sb, int wid, int lane,
                                          uint32_t wh, uint32_t wl, uint32_t ahh, uint32_t all) {
    int l7 = lane & 7, lg = lane >> 3, bl15 = lane & 15;
#pragma unroll
    for (int ks = 0; ks < 4; ks++) {
        uint32_t ah[4], al[4];
        int arow = (lg & 1) * 8 + l7;
        uint32_t aoff = sw128((uint32_t)(arow * 128 + ks * 32 + (lg >> 1) * 16));
        ldsm_x4(ah, sb + ahh + aoff);
        ldsm_x4(al, sb + all + aoff);
#pragma unroll
        for (int n = 0; n < 4; n++) {
            int brow = wid * 32 + n * 8 + (bl15 & 7);
            uint32_t boff = sw128((uint32_t)(brow * 128 + ks * 32 + (bl15 >> 3) * 16));
            uint32_t bh[2], bl_[2];
            ldsm_x2(bh, sb + wh + boff);
            ldsm_x2(bl_, sb + wl + boff);
            mma_bf16(acc[n], ah, bh);
            mma_bf16(acc[n], ah, bl_);
            mma_bf16(acc[n], al, bh);
        }
    }
}

// ---------------- K6: hop-0 via HMMA, 2 steps packed per neuron block ----------------
__global__ void __launch_bounds__(256) hop0_mma_kernel(const float* __restrict__ fcb,
                                                       const float* __restrict__ gW,
                                                       const float* __restrict__ gb) {
    int a = blockIdx.x >> 4, p = blockIdx.x & 15;
    int cnt = g_ncnt[a];
    if (2 * p >= cnt) return;
    extern __shared__ char smem[];
    uint32_t sb = smem_u32(smem);
    float* GATEs = (float*)(smem + T_GATE);
    int tid = threadIdx.x, wid = tid >> 5, lane = tid & 31;

    int e0 = g_nlist[a * Sc + 2 * p];
    bool has2 = (2 * p + 1 < cnt);
    int e1 = has2 ? g_nlist[a * Sc + 2 * p + 1] : e0;
    int s0 = e0 >> 8, k0 = e0 & 255;
    int s1 = e1 >> 8, k1 = e1 & 255;

    {
        int hw = tid >> 4, gl = tid & 15;
        int st = hw >> 3, b = hw & 7;
        int ss = st ? s1 : s0;
        const float* xp = g_x + (size_t)(ss * Bc + b) * Dc;
        const float* gwp = gW + (size_t)a * Dc;
        float gp = 0.f;
        for (int d = gl; d < Dc; d += 16) gp += xp[d] * gwp[d];
        for (int o = 8; o; o >>= 1) gp += __shfl_xor_sync(0xffffffffu, gp, o);
        if (gl == 0) GATEs[hw] = sigmoidf_(gp + gb[a]);
    }

    float acc[4][4];
#pragma unroll
    for (int n = 0; n < 4; n++)
#pragma unroll
        for (int q = 0; q < 4; q++) acc[n][q] = 0.f;

    for (int c = 0; c < 4; c++) {
        __syncthreads();
        for (int i = tid; i < 2048; i += 256) {
            int row = i >> 3, q = i & 7;
            size_t gi = ((size_t)a * Dc + row) * Dc + c * 64 + q * 8;
            uint32_t off = sw128((uint32_t)(row * 128 + q * 16));
            CP16(sb + T_WH + off, &g_fch[gi]);
            CP16(sb + T_WL + off, &g_fcl[gi]);
        }
        {
            int tl = tid >> 7, r = (tid >> 3) & 15, q = tid & 7;
            uint32_t off = sw128((uint32_t)(r * 128 + q * 16));
            uint32_t dst = sb + (tl ? T_AL : T_AH) + off;
            if (r < 8) {
                size_t gi = (size_t)(s0 * Bc + r) * Dc + c * 64 + q * 8;
                CP16(dst, &(tl ? g_xl : g_xh)[gi]);
            } else if (has2) {
                size_t gi = (size_t)(s1 * Bc + (r - 8)) * Dc + c * 64 + q * 8;
                CP16(dst, &(tl ? g_xl : g_xh)[gi]);
            } else {
                uint4 z = {0u, 0u, 0u, 0u};
                *(uint4*)(smem + (tl ? T_AL : T_AH) + off) = z;
            }
        }
        CPCOMMIT();
        CPWAIT();
        __syncthreads();
        mma_chunk(acc, sb, wid, lane, T_WH, T_WL, T_AH, T_AL);
    }
    __syncthreads();

    int b = lane >> 2, qc = 2 * (lane & 3);
    float gg0 = GATEs[b], gg1 = GATEs[8 + b];
    float w0 = g_w[(s0 * Bc + b) * Kc + k0];
    float w1 = has2 ? g_w[(s1 * Bc + b) * Kc + k1] : 0.f;
    size_t sb0 = (((size_t)(s0 * Kc + k0)) * Bc + b) * Dc;
    size_t sb1 = (((size_t)(s1 * Kc + k1)) * Bc + b) * Dc;
#pragma unroll
    for (int n = 0; n < 4; n++) {
        int col = wid * 32 + n * 8 + qc;
        float b0 = fcb[(size_t)a * Dc + col], b1 = fcb[(size_t)a * Dc + col + 1];
        {
            float v0 = gelu_exact(acc[n][0] + b0) * gg0 * w0;
            float v1 = gelu_exact(acc[n][1] + b1) * gg0 * w0;
            *(float2*)&g_states[sb0 + col] = make_float2(v0, v1);
            *(float2*)&g_nxt[sb0 + col] = make_float2(0.f, 0.f);
        }
        if (has2) {
            float v0 = gelu_exact(acc[n][2] + b0) * gg1 * w1;
            float v1 = gelu_exact(acc[n][3] + b1) * gg1 * w1;
            *(float2*)&g_states[sb1 + col] = make_float2(v0, v1);
            *(float2*)&g_nxt[sb1 + col] = make_float2(0.f, 0.f);
        }
    }
}

// ---------------- K7: edge pairs; both phases tf32, persistent grid ----------------
// smem: W dbl buffers [256][36]f at 0 / 36864; A dbl buffers [8][36]f at 73728 / 74880;
//       SIGA [8][260]f at 76032; SIGB at 84352; GATE[16] at 92672.
#define P1_W0 0
#define P1_W1 36864
#define P1_A0 73728
#define P1_A1 74880
#define E_SIGA 76032
#define E_SIGB 84352
#define E_GATE 92672
#define E_SMEM 92736

__device__ __forceinline__ void stage_w36(uint32_t sb, const float* __restrict__ W,
                                          size_t wbase, int c, int buf, int tid) {
    uint32_t wb = buf ? P1_W1 : P1_W0;
#pragma unroll
    for (int it = 0; it < 8; it++) {
        int i = it * 256 + tid;
        int row = i >> 3, q = i & 7;
        CP16(sb + wb + (uint32_t)(row * 36 + q * 4) * 4, W + wbase + (size_t)row * Dc + c * 32 + q * 4);
    }
}

__global__ void __launch_bounds__(256) edge_mma_kernel(const float* __restrict__ cW,
                                                       const float* __restrict__ fcW,
                                                       const float* __restrict__ fcb,
                                                       const float* __restrict__ gW,
                                                       const float* __restrict__ gb) {
    extern __shared__ char smem[];
    uint32_t sb = smem_u32(smem);
    float* GATEs = (float*)(smem + E_GATE);
    int tid = threadIdx.x, wid = tid >> 5, lane = tid & 31;
    int l4 = lane & 3, lq = lane >> 2;
    int npairs = g_pcnt;

    for (int p = blockIdx.x; p < npairs; p += gridDim.x) {
        int codeA = g_pairA[p];
        int codeB = g_pairB[p];
        int dst = g_pairD[p];
        bool hasB = (codeB >= 0);

        int sA = codeA >> 10, pdA = g_epd[codeA];
        int sB = hasB ? (codeB >> 10) : 0, pdB = hasB ? g_epd[codeB] : 0;

        // ---- phase 1 (per instance): SIG = states_src @ conn_W[e]^T, tf32 ----
        for (int which = 0; which < (hasB ? 2 : 1); which++) {
            int code = which ? codeB : codeA;
            int e = g_eid[code], ps = g_eps[code];
            int s = code >> 10;
            size_t abase = (((size_t)(s * Kc + ps)) * Bc) * Dc;
            size_t wbase = (size_t)e * Dc * Dc;
            float acc[4][4];
#pragma unroll
            for (int n = 0; n < 4; n++)
#pragma unroll
                for (int q = 0; q < 4; q++) acc[n][q] = 0.f;

            __syncthreads();  // previous use of W/A buffers done
            stage_w36(sb, cW, wbase, 0, 0, tid);
            if (tid < 64) {
                int r = tid >> 3, q = tid & 7;
                CP16(sb + P1_A0 + (uint32_t)(r * 36 + q * 4) * 4,
                     &g_states[abase + (size_t)r * Dc + q * 4]);
            }
            CPCOMMIT();
            for (int c = 0; c < 8; c++) {
                int cur = c & 1;
                if (c < 7) {
                    stage_w36(sb, cW, wbase, c + 1, cur ^ 1, tid);
                    if (tid < 64) {
                        int r = tid >> 3, q = tid & 7;
                        CP16(sb + (cur ? P1_A0 : P1_A1) + (uint32_t)(r * 36 + q * 4) * 4,
                             &g_states[abase + (size_t)r * Dc + (c + 1) * 32 + q * 4]);
                    }
                    CPCOMMIT();
                    CPWAIT1();
                } else {
                    CPWAIT();
                }
                __syncthreads();
                uint32_t wb = cur ? P1_W1 : P1_W0;
                uint32_t ab = cur ? P1_A1 : P1_A0;
#pragma unroll
                for (int ks = 0; ks < 4; ks++) {
                    uint32_t a0 = *(uint32_t*)(smem + ab + (uint32_t)(lq * 36 + ks * 8 + l4) * 4);
                    uint32_t a2 = *(uint32_t*)(smem + ab + (uint32_t)(lq * 36 + ks * 8 + l4 + 4) * 4);
#pragma unroll
                    for (int n = 0; n < 4; n++) {
                        int nn = wid * 32 + n * 8 + lq;
                        uint32_t b0 = *(uint32_t*)(smem + wb + (uint32_t)(nn * 36 + ks * 8 + l4) * 4);
                        uint32_t b1 = *(uint32_t*)(smem + wb + (uint32_t)(nn * 36 + ks * 8 + l4 + 4) * 4);
                        mma_tf32f(acc[n], a0, 0u, a2, 0u, b0, b1);
                    }
                }
                __syncthreads();
            }
            // write SIG + gate
            float* SIG = (float*)(smem + (which ? E_SIGB : E_SIGA));
            {
                int b = lane >> 2, qc = 2 * (lane & 3);
#pragma unroll
                for (int n = 0; n < 4; n++) {
                    int col = wid * 32 + n * 8 + qc;
                    SIG[b * 260 + col] = acc[n][0];
                    SIG[b * 260 + col + 1] = acc[n][1];
                }
            }
            __syncthreads();
            {
                int b = wid;
                const float* gwp = gW + (size_t)dst * Dc;
                float gp = 0.f;
                for (int d = lane; d < Dc; d += 32) gp += SIG[b * 260 + d] * gwp[d];
                for (int o = 16; o; o >>= 1) gp += __shfl_xor_sync(0xffffffffu, gp, o);
                if (lane == 0) GATEs[which * 8 + b] = sigmoidf_(gp + gb[dst]);
            }
        }

        // ---- phase 2: act = gelu(SIG @ fc_W[dst]^T + b) * gate, tf32, pair-packed ----
        float acc[4][4];
#pragma unroll
        for (int n = 0; n < 4; n++)
#pragma unroll
            for (int q = 0; q < 4; q++) acc[n][q] = 0.f;

        size_t fbase = (size_t)dst * Dc * Dc;
        const float* SIGA = (const float*)(smem + E_SIGA);
        const float* SIGB = (const float*)(smem + E_SIGB);
        __syncthreads();
        stage_w36(sb, fcW, fbase, 0, 0, tid);
        CPCOMMIT();
        for (int c = 0; c < 8; c++) {
            int cur = c & 1;
            if (c < 7) {
                stage_w36(sb, fcW, fbase, c + 1, cur ^ 1, tid);
                CPCOMMIT();
                CPWAIT1();
            } else {
                CPWAIT();
            }
            __syncthreads();
            uint32_t wb = cur ? P1_W1 : P1_W0;
#pragma unroll
            for (int ks = 0; ks < 4; ks++) {
                int kcol = c * 32 + ks * 8 + l4;
                uint32_t a0 = __float_as_uint(SIGA[lq * 260 + kcol]);
                uint32_t a2 = __float_as_uint(SIGA[lq * 260 + kcol + 4]);
                uint32_t a1 = hasB ? __float_as_uint(SIGB[lq * 260 + kcol]) : 0u;
                uint32_t a3 = hasB ? __float_as_uint(SIGB[lq * 260 + kcol + 4]) : 0u;
#pragma unroll
                for (int n = 0; n < 4; n++) {
                    int nn = wid * 32 + n * 8 + lq;
                    uint32_t b0 = *(uint32_t*)(smem + wb + (uint32_t)(nn * 36 + ks * 8 + l4) * 4);
                    uint32_t b1 = *(uint32_t*)(smem + wb + (uint32_t)(nn * 36 + ks * 8 + l4 + 4) * 4);
                    mma_tf32f(acc[n], a0, a1, a2, a3, b0, b1);
                }
            }
            __syncthreads();
        }

        // epilogue: c0/c1 -> instA, c2/c3 -> instB
        int b = lane >> 2, qc = 2 * (lane & 3);
        float ggA = GATEs[b];
        float ggB = hasB ? GATEs[8 + b] : 0.f;
        size_t nbA = (((size_t)(sA * Kc + pdA)) * Bc + b) * Dc;
        size_t nbB = (((size_t)(sB * Kc + pdB)) * Bc + b) * Dc;
#pragma unroll
        for (int n = 0; n < 4; n++) {
            int col = wid * 32 + n * 8 + qc;
            float b0 = fcb[(size_t)dst * Dc + col], b1 = fcb[(size_t)dst * Dc + col + 1];
            atomicAdd(&g_nxt[nbA + col], gelu_exact(acc[n][0] + b0) * ggA);
            atomicAdd(&g_nxt[nbA + col + 1], gelu_exact(acc[n][1] + b1) * ggA);
            if (hasB) {
                atomicAdd(&g_nxt[nbB + col], gelu_exact(acc[n][2] + b0) * ggB);
                atomicAdd(&g_nxt[nbB + col + 1], gelu_exact(acc[n][3] + b1) * ggB);
            }
        }
    }
}

// ---------------- K8: combine + LN ----------------
__global__ void combine_kernel(const float* __restrict__ lng, const float* __restrict__ lnb) {
    int s = blockIdx.x / Bc, b = blockIdx.x % Bc, d = threadIdx.x;
    float v = 0.f;
    for (int k = 0; k < Kc; k++) {
        size_t idx = (((size_t)(s * Kc + k)) * Bc + b) * Dc + d;
        v += g_states[idx] + 0.5f * g_nxt[idx];
    }
    v *= (1.0f / Kc);
    __shared__ float red[Dc];
    red[d] = v;
    __syncthreads();
    for (int o = Dc / 2; o; o >>= 1) {
        if (d < o) red[d] += red[d + o];
        __syncthreads();
    }
    float mu = red[0] * (1.0f / Dc);
    __syncthreads();
    float c = v - mu;
    red[d] = c * c;
    __syncthreads();
    for (int o = Dc / 2; o; o >>= 1) {
        if (d < o) red[d] += red[d + o];
        __syncthreads();
    }
    float var = red[0] * (1.0f / Dc);
    float y = c * rsqrtf(var + 1e-5f) * lng[d] + lnb[d];
    int row = b * Sc + s;
    __nv_bfloat16 h, l;
    split1(y, h, l);
    g_Ah[row * Dc + d] = h;
    g_Al[row * Dc + d] = l;
}

// ---------------- K9: bf16-split HMMA GEMM ----------
#define GA_H 0
#define GA_L 16384
#define GB_H 32768
#define GB_L 49152
#define G_BIAS 65536
#define G_SMEM (65536 + 512)

__global__ void __launch_bounds__(256, 2) gemm_mma_kernel(const float* __restrict__ ob,
                                                          float* __restrict__ out, int V) {
    extern __shared__ char smem[];
    uint32_t sb = smem_u32(smem);
    int tid = threadIdx.x, wid = tid >> 5, lane = tid & 31;
    int wm = wid >> 1, wn = wid & 1;
    int rb0 = blockIdx.x * 128;
    int cb = blockIdx.y * 128;

    float* bias = (float*)(smem + G_BIAS);
    if (tid < 128) bias[tid] = (cb + tid < V) ? ob[cb + tid] : 0.f;

    float acc[2][8][4];
#pragma unroll
    for (int mi = 0; mi < 2; mi++)
#pragma unroll
        for (int n = 0; n < 8; n++)
#pragma unroll
            for (int q = 0; q < 4; q++) acc[mi][n][q] = 0.f;

    for (int c = 0; c < 4; c++) {
        __syncthreads();
        for (int i = tid; i < 2048; i += 256) {
            int hl = i >> 10, rem = i & 1023, row = rem >> 3, q = rem & 7;
            uint32_t off = sw128((uint32_t)(row * 128 + q * 16));
            if (cb + row < V) {
                size_t gi = (size_t)(cb + row) * 256 + c * 64 + q * 8;
                CP16(sb + (hl ? GB_L : GB_H) + off, &(hl ? g_oWl : g_oWh)[gi]);
            } else {
                uint4 z = {0u, 0u, 0u, 0u};
                *(uint4*)(smem + (hl ? GB_L : GB_H) + off) = z;
            }
        }
#pragma unroll
        for (int it = 0; it < 8; it++) {
            int u = it * 256 + tid;
            int hl = u >> 10;
            int rem = u & 1023;
            int row = rem >> 3, q = rem & 7;
            size_t gi = (size_t)(rb0 + row) * 256 + c * 64 + q * 8;
            uint32_t off = sw128((uint32_t)(row * 128 + q * 16));
            CP16(sb + (hl ? GA_L : GA_H) + off, &(hl ? g_Al : g_Ah)[gi]);
        }
        CPCOMMIT();
        CPWAIT();
        __syncthreads();

        int l7 = lane & 7, lg = lane >> 3;
        int bl15 = lane & 15;
#pragma unroll
        for (int ks = 0; ks < 4; ks++) {
            uint32_t ah[2][4], al[2][4];
#pragma unroll
            for (int mi = 0; mi < 2; mi++) {
                int arow = wm * 32 + mi * 16 + (lg & 1) * 8 + l7;
                uint32_t aoff = sw128((uint32_t)(arow * 128 + ks * 32 + (lg >> 1) * 16));
                ldsm_x4(ah[mi], sb + GA_H + aoff);
                ldsm_x4(al[mi], sb + GA_L + aoff);
            }
#pragma unroll
            for (int n = 0; n < 8; n++) {
                int brow = wn * 64 + n * 8 + (bl15 & 7);
                uint32_t boff = sw128((uint32_t)(brow * 128 + ks * 32 + (bl15 >> 3) * 16));
                uint32_t bh[2], bl_[2];
                ldsm_x2(bh, sb + GB_H + boff);
                ldsm_x2(bl_, sb + GB_L + boff);
#pragma unroll
                for (int mi = 0; mi < 2; mi++) {
                    mma_bf16(acc[mi][n], ah[mi], bh);
                    mma_bf16(acc[mi][n], ah[mi], bl_);
                    mma_bf16(acc[mi][n], al[mi], bh);
                }
            }
        }
    }

    int qrow = lane >> 2, qcol = 2 * (lane & 3);
#pragma unroll
    for (int mi = 0; mi < 2; mi++) {
#pragma unroll
        for (int n = 0; n < 8; n++) {
            int lcol = wn * 64 + n * 8 + qcol;
            int gc = cb + lcol;
            int gr = rb0 + wm * 32 + mi * 16 + qrow;
            float b0 = bias[lcol], b1 = bias[lcol + 1];
            size_t base0 = (size_t)gr * V + gc;
            size_t base1 = (size_t)(gr + 8) * V + gc;
            if (gc < V) {
                out[base0] = acc[mi][n][0] + b0;
                out[base1] = acc[mi][n][2] + b0;
            }
            if (gc + 1 < V) {
                out[base0 + 1] = acc[mi][n][1] + b1;
                out[base1 + 1] = acc[mi][n][3] + b1;
            }
        }
    }
}

// ---------------- launcher ----------------
extern "C" void kernel_launch(void* const* d_in, const int* in_sizes, int n_in,
                              void* d_out, int out_size) {
    const int*   ids   = (const int*)d_in[0];
    const float* embed = (const float*)d_in[1];
    const float* pos   = (const float*)d_in[2];
    const float* rW    = (const float*)d_in[3];
    const float* rb    = (const float*)d_in[4];
    const float* fcW   = (const float*)d_in[5];
    const float* fcb   = (const float*)d_in[6];
    const float* gW    = (const float*)d_in[7];
    const float* gb    = (const float*)d_in[8];
    const float* cW    = (const float*)d_in[9];
    const float* lng   = (const float*)d_in[10];
    const float* lnb   = (const float*)d_in[11];
    const float* oW    = (const float*)d_in[12];
    const float* ob    = (const float*)d_in[13];
    const int*   esrc  = (const int*)d_in[14];
    const int*   edst  = (const int*)d_in[15];
    int E = in_sizes[14];
    int V = in_sizes[12] / Dc;
    float* out = (float*)d_out;

    convert_fc_kernel<<<(Nc * Dc * Dc / 8 + 255) / 256, 256>>>(fcW);
    {
        int vc = V < VMAX ? V : VMAX;
        convert_ow_kernel<<<((vc * Dc) / 8 + 255) / 256, 256>>>(oW, vc);
    }

    embed_kernel<<<Sc * Bc, Dc>>>(ids, embed, pos);
    {
        dim3 rg(Sc, 4);
        router_kernel<<<rg, 256>>>(rW, rb);
    }
    topk_kernel<<<(Sc * Bc) / 4, 128>>>();
    build_groups_kernel<<<Nc, 256>>>();
    efilter_kernel<<<Sc, 256>>>(esrc, edst, E);
    sort_pairs_kernel<<<1, 256>>>();

    cudaFuncSetAttribute(hop0_mma_kernel, cudaFuncAttributeMaxDynamicSharedMemorySize, H_SMEM);
    hop0_mma_kernel<<<Nc * 16, 256, H_SMEM>>>(fcb, gW, gb);

    cudaFuncSetAttribute(edge_mma_kernel, cudaFuncAttributeMaxDynamicSharedMemorySize, E_SMEM);
    edge_mma_kernel<<<740, 256, E_SMEM>>>(cW, fcW, fcb, gW, gb);

    combine_kernel<<<Sc * Bc, Dc>>>(lng, lnb);

    cudaFuncSetAttribute(gemm_mma_kernel, cudaFuncAttributeMaxDynamicSharedMemorySize, G_SMEM);
    dim3 g(2, (V + 127) / 128);
    gemm_mma_kernel<<<g, 256, G_SMEM>>>(ob, out, V);
}

// round 15
// speedup vs baseline: 1.0484x; 1.0484x over previous
#include <cuda_runtime.h>
#include <cuda_bf16.h>
#include <math.h>
#include <stdint.h>

#define Bc 8
#define Sc 32
#define Dc 256
#define Nc 256
#define Kc 51
#define EMAX 1024
#define VMAX 50432

// ---------------- scratch ----------------
__device__ float g_x[Sc * Bc * Dc];
__device__ float g_scores[Sc * Bc * Nc];
__device__ float g_w[Sc * Bc * Kc];
__device__ int   g_active[Sc * Kc];
__device__ int   g_gecnt;
__device__ int   g_glist[Sc * EMAX];
__device__ int   g_eid[Sc * EMAX];
__device__ int   g_eps[Sc * EMAX];
__device__ int   g_epd[Sc * EMAX];
__device__ int   g_ncnt[Nc];
__device__ int   g_nlist[Nc * Sc];
__device__ float g_states[Sc * Kc * Bc * Dc];
__device__ float g_nxt[Sc * Kc * Bc * Dc];
__device__ __align__(16) __nv_bfloat16 g_Ah[256 * 256];
__device__ __align__(16) __nv_bfloat16 g_Al[256 * 256];
__device__ __align__(16) __nv_bfloat16 g_xh[Sc * Bc * Dc];
__device__ __align__(16) __nv_bfloat16 g_xl[Sc * Bc * Dc];
__device__ __align__(16) __nv_bfloat16 g_fch[Nc * Dc * Dc];
__device__ __align__(16) __nv_bfloat16 g_fcl[Nc * Dc * Dc];
__device__ __align__(16) __nv_bfloat16 g_oWh[VMAX * Dc];
__device__ __align__(16) __nv_bfloat16 g_oWl[VMAX * Dc];

// ---------------- side stream (created at static init: no mem delta mid-run) ----
static cudaStream_t g_s2;
static cudaEvent_t g_evFork, g_evJoin;
namespace {
struct _InitStreams {
    _InitStreams() {
        cudaStreamCreateWithFlags(&g_s2, cudaStreamNonBlocking);
        cudaEventCreateWithFlags(&g_evFork, cudaEventDisableTiming);
        cudaEventCreateWithFlags(&g_evJoin, cudaEventDisableTiming);
    }
};
_InitStreams _initStreams;
}  // namespace

// ---------------- helpers ----------------
__device__ __forceinline__ float gelu_exact(float x) {
    return 0.5f * x * (1.0f + erff(x * 0.70710678118654752440f));
}
__device__ __forceinline__ float sigmoidf_(float x) {
    return 1.0f / (1.0f + expf(-x));
}
__device__ __forceinline__ unsigned long long ullmax_(unsigned long long a, unsigned long long b) {
    return a > b ? a : b;
}
__device__ __forceinline__ uint32_t smem_u32(const void* p) {
    uint32_t a;
    asm("{ .reg .u64 t; cvta.to.shared.u64 t, %1; cvt.u32.u64 %0, t; }" : "=r"(a) : "l"(p));
    return a;
}
__device__ __forceinline__ uint32_t sw128(uint32_t o) { return o ^ ((o >> 3) & 0x70); }

#define CP16(saddr, gptr) \
    asm volatile("cp.async.ca.shared.global [%0], [%1], 16;" :: "r"(saddr), "l"(gptr))
#define CPCOMMIT() asm volatile("cp.async.commit_group;")
#define CPWAIT() asm volatile("cp.async.wait_group 0;" ::: "memory")
#define CPWAIT1() asm volatile("cp.async.wait_group 1;" ::: "memory")

__device__ __forceinline__ void packpair(float a, float b, uint32_t& h, uint32_t& l) {
    uint32_t ua = __float_as_uint(a), ub = __float_as_uint(b);
    asm("prmt.b32 %0, %1, %2, 0x7632;" : "=r"(h) : "r"(ua), "r"(ub));
    float la = a - __uint_as_float(ua & 0xFFFF0000u);
    float lb = b - __uint_as_float(ub & 0xFFFF0000u);
    uint32_t ula = __float_as_uint(la), ulb = __float_as_uint(lb);
    asm("prmt.b32 %0, %1, %2, 0x7632;" : "=r"(l) : "r"(ula), "r"(ulb));
}
__device__ __forceinline__ void split1(float a, __nv_bfloat16& h, __nv_bfloat16& l) {
    uint32_t ua = __float_as_uint(a);
    uint16_t hb = (uint16_t)(ua >> 16);
    float lo = a - __uint_as_float(ua & 0xFFFF0000u);
    uint16_t lb = (uint16_t)(__float_as_uint(lo) >> 16);
    h = *(__nv_bfloat16*)&hb;
    l = *(__nv_bfloat16*)&lb;
}

__device__ __forceinline__ void ldsm_x4(uint32_t* r, uint32_t addr) {
    asm volatile("ldmatrix.sync.aligned.m8n8.x4.shared.b16 {%0,%1,%2,%3}, [%4];"
                 : "=r"(r[0]), "=r"(r[1]), "=r"(r[2]), "=r"(r[3]) : "r"(addr));
}
__device__ __forceinline__ void ldsm_x2(uint32_t* r, uint32_t addr) {
    asm volatile("ldmatrix.sync.aligned.m8n8.x2.shared.b16 {%0,%1}, [%2];"
                 : "=r"(r[0]), "=r"(r[1]) : "r"(addr));
}
__device__ __forceinline__ void mma_bf16(float* d, const uint32_t* a, const uint32_t* b) {
    asm volatile(
        "mma.sync.aligned.m16n8k16.row.col.f32.bf16.bf16.f32 "
        "{%0,%1,%2,%3}, {%4,%5,%6,%7}, {%8,%9}, {%0,%1,%2,%3};"
        : "+f"(d[0]), "+f"(d[1]), "+f"(d[2]), "+f"(d[3])
        : "r"(a[0]), "r"(a[1]), "r"(a[2]), "r"(a[3]), "r"(b[0]), "r"(b[1]));
}
__device__ __forceinline__ void mma_tf32(float* d, uint32_t a0, uint32_t a2,
                                         uint32_t b0, uint32_t b1) {
    asm volatile(
        "mma.sync.aligned.m16n8k8.row.col.f32.tf32.tf32.f32 "
        "{%0,%1,%2,%3}, {%4,%5,%6,%7}, {%8,%9}, {%0,%1,%2,%3};"
        : "+f"(d[0]), "+f"(d[1]), "+f"(d[2]), "+f"(d[3])
        : "r"(a0), "r"(0u), "r"(a2), "r"(0u), "r"(b0), "r"(b1));
}

// ---------------- weight converters + nxt zeroing (side stream) ----------------
__global__ void convert_fc_kernel(const float* __restrict__ fcW) {
    size_t i = ((size_t)blockIdx.x * 256 + threadIdx.x) * 8;
    const float4* s4 = (const float4*)(fcW + i);
    float4 w0 = s4[0], w1 = s4[1];
    uint4 h, l;
    packpair(w0.x, w0.y, h.x, l.x);
    packpair(w0.z, w0.w, h.y, l.y);
    packpair(w1.x, w1.y, h.z, l.z);
    packpair(w1.z, w1.w, h.w, l.w);
    *(uint4*)&g_fch[i] = h;
    *(uint4*)&g_fcl[i] = l;
}
__global__ void convert_ow_kernel(const float* __restrict__ oW, int V) {
    size_t i = ((size_t)blockIdx.x * 256 + threadIdx.x) * 8;
    if (i >= (size_t)V * Dc || i >= (size_t)VMAX * Dc) return;
    const float4* s4 = (const float4*)(oW + i);
    float4 w0 = s4[0], w1 = s4[1];
    uint4 h, l;
    packpair(w0.x, w0.y, h.x, l.x);
    packpair(w0.z, w0.w, h.y, l.y);
    packpair(w1.x, w1.y, h.z, l.z);
    packpair(w1.z, w1.w, h.w, l.w);
    *(uint4*)&g_oWh[i] = h;
    *(uint4*)&g_oWl[i] = l;
}
__global__ void zero_nxt_kernel() {
    size_t i = ((size_t)blockIdx.x * 256 + threadIdx.x) * 4;
    *(float4*)&g_nxt[i] = make_float4(0.f, 0.f, 0.f, 0.f);
}

// ---------------- K1: embed ----------------
__global__ void embed_kernel(const int* __restrict__ ids,
                             const float* __restrict__ embed,
                             const float* __restrict__ pos) {
    int s = blockIdx.x / Bc, b = blockIdx.x % Bc, d = threadIdx.x;
    int id = ids[b * Sc + s];
    float v = embed[(size_t)id * Dc + d] + pos[s * Dc + d];
    int idx = (s * Bc + b) * Dc + d;
    g_x[idx] = v;
    __nv_bfloat16 h, l;
    split1(v, h, l);
    g_xh[idx] = h;
    g_xl[idx] = l;
}

// ---------------- K2: router (grid Sc x 4; 4 threads/neuron) ----------------
__global__ void __launch_bounds__(256) router_kernel(const float* __restrict__ rW,
                                                     const float* __restrict__ rb) {
    __shared__ float xs[Bc][Dc];
    int s = blockIdx.x;
    int t = threadIdx.x;
    for (int i = t; i < Bc * Dc; i += 256) xs[i >> 8][i & 255] = g_x[s * Bc * Dc + i];
    __syncthreads();
    int neuron = blockIdx.y * 64 + (t >> 2), part = t & 3;
    const float4* w4 = (const float4*)(rW + (size_t)neuron * Dc + part * 64);
    float acc[Bc];
#pragma unroll
    for (int b = 0; b < Bc; b++) acc[b] = 0.f;
#pragma unroll
    for (int q = 0; q < 16; q++) {
        float4 w = w4[q];
#pragma unroll
        for (int b = 0; b < Bc; b++) {
            float4 xv = *(const float4*)&xs[b][part * 64 + 4 * q];
            acc[b] += w.x * xv.x + w.y * xv.y + w.z * xv.z + w.w * xv.w;
        }
    }
#pragma unroll
    for (int o = 1; o <= 2; o <<= 1)
#pragma unroll
        for (int b = 0; b < Bc; b++) acc[b] += __shfl_xor_sync(0xffffffffu, acc[b], o);
    if (part == 0) {
        float bias = rb[neuron];
#pragma unroll
        for (int b = 0; b < Bc; b++) g_scores[(s * Bc + b) * Nc + neuron] = acc[b] + bias;
    }
}

// ---------------- K3: top-K ----------------
__global__ void topk_kernel() {
    int wid = threadIdx.x >> 5, lane = threadIdx.x & 31;
    int row = blockIdx.x * 4 + wid;
    int s = row / Bc, b = row % Bc;
    const float* sc = g_scores + row * Nc;

    unsigned long long key[Nc / 32];
#pragma unroll
    for (int j = 0; j < Nc / 32; j++) {
        int idx = j * 32 + lane;
        unsigned bits = __float_as_uint(sc[idx]);
        unsigned u = (bits & 0x80000000u) ? ~bits : (bits | 0x80000000u);
        key[j] = ((unsigned long long)u << 32) | (unsigned)(Nc - 1 - idx);
    }
    __shared__ float vals[4][Kc];
    for (int k = 0; k < Kc; k++) {
        unsigned long long m = key[0];
#pragma unroll
        for (int j = 1; j < Nc / 32; j++) m = ullmax_(m, key[j]);
        for (int o = 16; o; o >>= 1) m = ullmax_(m, __shfl_xor_sync(0xffffffffu, m, o));
        int idx = Nc - 1 - (int)(unsigned)(m & 0xffffffffu);
        if ((idx & 31) == lane) key[idx >> 5] = 0ull;
        unsigned u = (unsigned)(m >> 32);
        unsigned bits = (u & 0x80000000u) ? (u ^ 0x80000000u) : ~u;
        if (lane == 0) {
            vals[wid][k] = __uint_as_float(bits);
            if (b == 0) g_active[s * Kc + k] = idx;
        }
    }
    __syncwarp();
    float v0 = vals[wid][0];
    float e1 = (lane < Kc) ? expf(vals[wid][lane] - v0) : 0.f;
    float e2 = (lane + 32 < Kc) ? expf(vals[wid][lane + 32] - v0) : 0.f;
    float ssum = e1 + e2;
    for (int o = 16; o; o >>= 1) ssum += __shfl_xor_sync(0xffffffffu, ssum, o);
    float inv = 1.0f / ssum;
    if (lane < Kc) g_w[row * Kc + lane] = e1 * inv;
    if (lane + 32 < Kc) g_w[row * Kc + lane + 32] = e2 * inv;
}

// ---------------- K3b: group hop0 instances by neuron; zero global edge count ----
__global__ void build_groups_kernel() {
    int a = blockIdx.x;
    if (a == 0 && threadIdx.x == 0) g_gecnt = 0;
    __shared__ int cnt;
    if (threadIdx.x == 0) cnt = 0;
    __syncthreads();
    for (int i = threadIdx.x; i < Sc * Kc; i += blockDim.x) {
        if (g_active[i] == a) {
            int s = i / Kc, k = i - s * Kc;
            int slot = atomicAdd(&cnt, 1);
            g_nlist[a * Sc + slot] = (s << 8) | k;
        }
    }
    __syncthreads();
    if (threadIdx.x == 0) g_ncnt[a] = cnt;
}

// ---------------- K5: compact active edges (pos in smem, global list) ----------------
__global__ void __launch_bounds__(256) efilter_kernel(const int* __restrict__ esrc,
                                                      const int* __restrict__ edst, int E) {
    __shared__ int pos[Nc];
    __shared__ int cnt;
    int s = blockIdx.x, t = threadIdx.x;
    pos[t] = -1;
    if (t == 0) cnt = 0;
    __syncthreads();
    if (t < Kc) pos[g_active[s * Kc + t]] = t;
    __syncthreads();
    for (int e = t; e < E; e += 256) {
        int ps = pos[esrc[e]];
        int pd = pos[edst[e]];
        if (ps >= 0 && pd >= 0) {
            int slot = atomicAdd(&cnt, 1);
            int code = s * EMAX + slot;
            g_eid[code] = e;
            g_eps[code] = ps;
            g_epd[code] = pd;
            int g = atomicAdd(&g_gecnt, 1);
            g_glist[g] = code;
        }
    }
}

// ======== HMMA small-M tile machinery (hop0) ========
#define T_WH 0
#define T_WL 32768
#define T_AH 65536
#define T_AL 67584
#define T_GATE 69632
#define H_SMEM (69632 + 64)
// edge layout:
//   phase1: W dbl buffers [256][36]f at 0 / 36864; A dbl buffers [8][36]f at 73728 / 74880
//   post-phase1: SIG [8][256] fp32 at 0; GATE at 8192
//   phase2 (bf16): WH 9216, WL 41984, AH 74752, AL 76800  (end 78848)
#define P1_W0 0
#define P1_W1 36864
#define P1_A0 73728
#define P1_A1 74880
#define E_SIG 0
#define E_GATE 8192
#define T2_WH 9216
#define T2_WL 41984
#define T2_AH 74752
#define T2_AL 76800
#define E_SMEM 78848

__device__ __forceinline__ void mma_chunk(float acc[4][4], uint32_t sb, int wid, int lane,
                                          uint32_t wh, uint32_t wl, uint32_t ahh, uint32_t all) {
    int l7 = lane & 7, lg = lane >> 3, bl15 = lane & 15;
#pragma unroll
    for (int ks = 0; ks < 4; ks++) {
        uint32_t ah[4], al[4];
        int arow = (lg & 1) * 8 + l7;
        uint32_t aoff = sw128((uint32_t)(arow * 128 + ks * 32 + (lg >> 1) * 16));
        ldsm_x4(ah, sb + ahh + aoff);
        ldsm_x4(al, sb + all + aoff);
#pragma unroll
        for (int n = 0; n < 4; n++) {
            int brow = wid * 32 + n * 8 + (bl15 & 7);
            uint32_t boff = sw128((uint32_t)(brow * 128 + ks * 32 + (bl15 >> 3) * 16));
            uint32_t bh[2], bl_[2];
            ldsm_x2(bh, sb + wh + boff);
            ldsm_x2(bl_, sb + wl + boff);
            mma_bf16(acc[n], ah, bh);
            mma_bf16(acc[n], ah, bl_);
            mma_bf16(acc[n], al, bh);
        }
    }
}

// ---------------- K6: hop-0 via HMMA, 2 steps packed per neuron block ----------------
__global__ void __launch_bounds__(256) hop0_mma_kernel(const float* __restrict__ fcb,
                                                       const float* __restrict__ gW,
                                                       const float* __restrict__ gb) {
    int a = blockIdx.x >> 4, p = blockIdx.x & 15;
    int cnt = g_ncnt[a];
    if (2 * p >= cnt) return;
    extern __shared__ char smem[];
    uint32_t sb = smem_u32(smem);
    float* GATEs = (float*)(smem + T_GATE);
    int tid = threadIdx.x, wid = tid >> 5, lane = tid & 31;

    int e0 = g_nlist[a * Sc + 2 * p];
    bool has2 = (2 * p + 1 < cnt);
    int e1 = has2 ? g_nlist[a * Sc + 2 * p + 1] : e0;
    int s0 = e0 >> 8, k0 = e0 & 255;
    int s1 = e1 >> 8, k1 = e1 & 255;

    {
        int hw = tid >> 4, gl = tid & 15;
        int st = hw >> 3, b = hw & 7;
        int ss = st ? s1 : s0;
        const float* xp = g_x + (size_t)(ss * Bc + b) * Dc;
        const float* gwp = gW + (size_t)a * Dc;
        float gp = 0.f;
        for (int d = gl; d < Dc; d += 16) gp += xp[d] * gwp[d];
        for (int o = 8; o; o >>= 1) gp += __shfl_xor_sync(0xffffffffu, gp, o);
        if (gl == 0) GATEs[hw] = sigmoidf_(gp + gb[a]);
    }

    float acc[4][4];
#pragma unroll
    for (int n = 0; n < 4; n++)
#pragma unroll
        for (int q = 0; q < 4; q++) acc[n][q] = 0.f;

    for (int c = 0; c < 4; c++) {
        __syncthreads();
        for (int i = tid; i < 2048; i += 256) {
            int row = i >> 3, q = i & 7;
            size_t gi = ((size_t)a * Dc + row) * Dc + c * 64 + q * 8;
            uint32_t off = sw128((uint32_t)(row * 128 + q * 16));
            CP16(sb + T_WH + off, &g_fch[gi]);
            CP16(sb + T_WL + off, &g_fcl[gi]);
        }
        {
            int tl = tid >> 7, r = (tid >> 3) & 15, q = tid & 7;
            uint32_t off = sw128((uint32_t)(r * 128 + q * 16));
            uint32_t dst = sb + (tl ? T_AL : T_AH) + off;
            if (r < 8) {
                size_t gi = (size_t)(s0 * Bc + r) * Dc + c * 64 + q * 8;
                CP16(dst, &(tl ? g_xl : g_xh)[gi]);
            } else if (has2) {
                size_t gi = (size_t)(s1 * Bc + (r - 8)) * Dc + c * 64 + q * 8;
                CP16(dst, &(tl ? g_xl : g_xh)[gi]);
            } else {
                uint4 z = {0u, 0u, 0u, 0u};
                *(uint4*)(smem + (tl ? T_AL : T_AH) + off) = z;
            }
        }
        CPCOMMIT();
        CPWAIT();
        __syncthreads();
        mma_chunk(acc, sb, wid, lane, T_WH, T_WL, T_AH, T_AL);
    }
    __syncthreads();

    int b = lane >> 2, qc = 2 * (lane & 3);
    float gg0 = GATEs[b], gg1 = GATEs[8 + b];
    float w0 = g_w[(s0 * Bc + b) * Kc + k0];
    float w1 = has2 ? g_w[(s1 * Bc + b) * Kc + k1] : 0.f;
    size_t sb0 = (((size_t)(s0 * Kc + k0)) * Bc + b) * Dc;
    size_t sb1 = (((size_t)(s1 * Kc + k1)) * Bc + b) * Dc;
#pragma unroll
    for (int n = 0; n < 4; n++) {
        int col = wid * 32 + n * 8 + qc;
        float b0 = fcb[(size_t)a * Dc + col], b1 = fcb[(size_t)a * Dc + col + 1];
        {
            float v0 = gelu_exact(acc[n][0] + b0) * gg0 * w0;
            float v1 = gelu_exact(acc[n][1] + b1) * gg0 * w0;
            *(float2*)&g_states[sb0 + col] = make_float2(v0, v1);
        }
        if (has2) {
            float v0 = gelu_exact(acc[n][2] + b0) * gg1 * w1;
            float v1 = gelu_exact(acc[n][3] + b1) * gg1 * w1;
            *(float2*)&g_states[sb1 + col] = make_float2(v0, v1);
        }
    }
}

// ---------------- K7: edges; persistent grid; phase1 tf32 double-buffered ----
__device__ __forceinline__ void edge_stage_p1(uint32_t sb, const float* __restrict__ cW,
                                              int e, size_t abase, int c, int buf, int tid) {
    uint32_t wbase = buf ? P1_W1 : P1_W0;
    uint32_t abuf = buf ? P1_A1 : P1_A0;
#pragma unroll
    for (int it = 0; it < 8; it++) {
        int i = it * 256 + tid;
        int row = i >> 3, q = i & 7;
        CP16(sb + wbase + (uint32_t)(row * 36 + q * 4) * 4,
             &cW[((size_t)e * Dc + row) * Dc + c * 32 + q * 4]);
    }
    if (tid < 64) {
        int r = tid >> 3, q = tid & 7;
        CP16(sb + abuf + (uint32_t)(r * 36 + q * 4) * 4,
             &g_states[abase + (size_t)r * Dc + c * 32 + q * 4]);
    }
}

__global__ void __launch_bounds__(256) edge_mma_kernel(const float* __restrict__ cW,
                                                       const float* __restrict__ fcb,
                                                       const float* __restrict__ gW,
                                                       const float* __restrict__ gb,
                                                       const int* __restrict__ edst) {
    extern __shared__ char smem[];
    uint32_t sb = smem_u32(smem);
    float* SIG = (float*)(smem + E_SIG);
    float* GATEs = (float*)(smem + E_GATE);
    int tid = threadIdx.x, wid = tid >> 5, lane = tid & 31;
    int total = g_gecnt;

    for (int idx = blockIdx.x; idx < total; idx += gridDim.x) {
        int code = g_glist[idx];
        int e = g_eid[code];
        int ps = g_eps[code];
        int pd = g_epd[code];
        int s = code >> 10;  // EMAX = 1024
        int dst = edst[e];

        float acc[4][4];
#pragma unroll
        for (int n = 0; n < 4; n++)
#pragma unroll
            for (int q = 0; q < 4; q++) acc[n][q] = 0.f;

        // ---- phase 1: tf32 raw-bits, 8 K-chunks of 32, double-buffered ----
        size_t abase = (((size_t)(s * Kc + ps)) * Bc) * Dc;
        int l4 = lane & 3, lq = lane >> 2;
        __syncthreads();  // prior iteration fully done before restaging
        edge_stage_p1(sb, cW, e, abase, 0, 0, tid);
        CPCOMMIT();
        for (int c = 0; c < 8; c++) {
            int cur = c & 1;
            if (c < 7) {
                edge_stage_p1(sb, cW, e, abase, c + 1, cur ^ 1, tid);
                CPCOMMIT();
                CPWAIT1();
            } else {
                CPWAIT();
            }
            __syncthreads();
            uint32_t wbase = cur ? P1_W1 : P1_W0;
            uint32_t abuf = cur ? P1_A1 : P1_A0;
#pragma unroll
            for (int ks = 0; ks < 4; ks++) {
                uint32_t a0 = *(uint32_t*)(smem + abuf + (uint32_t)(lq * 36 + ks * 8 + l4) * 4);
                uint32_t a2 = *(uint32_t*)(smem + abuf + (uint32_t)(lq * 36 + ks * 8 + l4 + 4) * 4);
#pragma unroll
                for (int n = 0; n < 4; n++) {
                    int nn = wid * 32 + n * 8 + lq;
                    uint32_t b0 = *(uint32_t*)(smem + wbase + (uint32_t)(nn * 36 + ks * 8 + l4) * 4);
                    uint32_t b1 = *(uint32_t*)(smem + wbase + (uint32_t)(nn * 36 + ks * 8 + l4 + 4) * 4);
                    mma_tf32(acc[n], a0, a2, b0, b1);
                }
            }
            __syncthreads();  // mma reads done before this buffer is restaged
        }
        // SIG (overwrites dead W region at offset 0)
        {
            int b = lane >> 2, qc = 2 * (lane & 3);
#pragma unroll
            for (int n = 0; n < 4; n++) {
                int col = wid * 32 + n * 8 + qc;
                SIG[b * Dc + col] = acc[n][0];
                SIG[b * Dc + col + 1] = acc[n][1];
            }
        }
        __syncthreads();

        // gate from sig
        {
            int b = wid;
            const float* gwp = gW + (size_t)dst * Dc;
            float gp = 0.f;
            for (int d = lane; d < Dc; d += 32) gp += SIG[b * Dc + d] * gwp[d];
            for (int o = 16; o; o >>= 1) gp += __shfl_xor_sync(0xffffffffu, gp, o);
            if (lane == 0) GATEs[b] = sigmoidf_(gp + gb[dst]);
        }

        // ---- phase 2: bf16 3-pass ----
#pragma unroll
        for (int n = 0; n < 4; n++)
#pragma unroll
            for (int q = 0; q < 4; q++) acc[n][q] = 0.f;

        for (int c = 0; c < 4; c++) {
            __syncthreads();
            for (int i = tid; i < 2048; i += 256) {
                int row = i >> 3, q = i & 7;
                size_t gi = ((size_t)dst * Dc + row) * Dc + c * 64 + q * 8;
                uint32_t off = sw128((uint32_t)(row * 128 + q * 16));
                CP16(sb + T2_WH + off, &g_fch[gi]);
                CP16(sb + T2_WL + off, &g_fcl[gi]);
            }
            CPCOMMIT();
            if (tid < 128) {
                int r = tid >> 3, q = tid & 7;
                uint4 h = {0u, 0u, 0u, 0u}, l = {0u, 0u, 0u, 0u};
                if (r < 8) {
                    const float* sp = &SIG[r * Dc + c * 64 + q * 8];
                    packpair(sp[0], sp[1], h.x, l.x);
                    packpair(sp[2], sp[3], h.y, l.y);
                    packpair(sp[4], sp[5], h.z, l.z);
                    packpair(sp[6], sp[7], h.w, l.w);
                }
                uint32_t off = sw128((uint32_t)(r * 128 + q * 16));
                *(uint4*)(smem + T2_AH + off) = h;
                *(uint4*)(smem + T2_AL + off) = l;
            }
            CPWAIT();
            __syncthreads();
            mma_chunk(acc, sb, wid, lane, T2_WH, T2_WL, T2_AH, T2_AL);
        }
        __syncthreads();

        int b = lane >> 2, qc = 2 * (lane & 3);
        float gg = GATEs[b];
        size_t nbase = (((size_t)(s * Kc + pd)) * Bc + b) * Dc;
#pragma unroll
        for (int n = 0; n < 4; n++) {
            int col = wid * 32 + n * 8 + qc;
            float b0 = fcb[(size_t)dst * Dc + col], b1 = fcb[(size_t)dst * Dc + col + 1];
            atomicAdd(&g_nxt[nbase + col], gelu_exact(acc[n][0] + b0) * gg);
            atomicAdd(&g_nxt[nbase + col + 1], gelu_exact(acc[n][1] + b1) * gg);
        }
    }
}

// ---------------- K8: combine + LN ----------------
__global__ void combine_kernel(const float* __restrict__ lng, const float* __restrict__ lnb) {
    int s = blockIdx.x / Bc, b = blockIdx.x % Bc, d = threadIdx.x;
    float v = 0.f;
    for (int k = 0; k < Kc; k++) {
        size_t idx = (((size_t)(s * Kc + k)) * Bc + b) * Dc + d;
        v += g_states[idx] + 0.5f * g_nxt[idx];
    }
    v *= (1.0f / Kc);
    __shared__ float red[Dc];
    red[d] = v;
    __syncthreads();
    for (int o = Dc / 2; o; o >>= 1) {
        if (d < o) red[d] += red[d + o];
        __syncthreads();
    }
    float mu = red[0] * (1.0f / Dc);
    __syncthreads();
    float c = v - mu;
    red[d] = c * c;
    __syncthreads();
    for (int o = Dc / 2; o; o >>= 1) {
        if (d < o) red[d] += red[d + o];
        __syncthreads();
    }
    float var = red[0] * (1.0f / Dc);
    float y = c * rsqrtf(var + 1e-5f) * lng[d] + lnb[d];
    int row = b * Sc + s;
    __nv_bfloat16 h, l;
    split1(y, h, l);
    g_Ah[row * Dc + d] = h;
    g_Al[row * Dc + d] = l;
}

// ---------------- K9: bf16-split HMMA GEMM ----------
#define GA_H 0
#define GA_L 16384
#define GB_H 32768
#define GB_L 49152
#define G_BIAS 65536
#define G_SMEM (65536 + 512)

__global__ void __launch_bounds__(256, 2) gemm_mma_kernel(const float* __restrict__ ob,
                                                          float* __restrict__ out, int V) {
    extern __shared__ char smem[];
    uint32_t sb = smem_u32(smem);
    int tid = threadIdx.x, wid = tid >> 5, lane = tid & 31;
    int wm = wid >> 1, wn = wid & 1;
    int rb0 = blockIdx.x * 128;
    int cb = blockIdx.y * 128;

    float* bias = (float*)(smem + G_BIAS);
    if (tid < 128) bias[tid] = (cb + tid < V) ? ob[cb + tid] : 0.f;

    float acc[2][8][4];
#pragma unroll
    for (int mi = 0; mi < 2; mi++)
#pragma unroll
        for (int n = 0; n < 8; n++)
#pragma unroll
            for (int q = 0; q < 4; q++) acc[mi][n][q] = 0.f;

    for (int c = 0; c < 4; c++) {
        __syncthreads();
        for (int i = tid; i < 2048; i += 256) {
            int hl = i >> 10, rem = i & 1023, row = rem >> 3, q = rem & 7;
            uint32_t off = sw128((uint32_t)(row * 128 + q * 16));
            if (cb + row < V) {
                size_t gi = (size_t)(cb + row) * 256 + c * 64 + q * 8;
                CP16(sb + (hl ? GB_L : GB_H) + off, &(hl ? g_oWl : g_oWh)[gi]);
            } else {
                uint4 z = {0u, 0u, 0u, 0u};
                *(uint4*)(smem + (hl ? GB_L : GB_H) + off) = z;
            }
        }
#pragma unroll
        for (int it = 0; it < 8; it++) {
            int u = it * 256 + tid;
            int hl = u >> 10;
            int rem = u & 1023;
            int row = rem >> 3, q = rem & 7;
            size_t gi = (size_t)(rb0 + row) * 256 + c * 64 + q * 8;
            uint32_t off = sw128((uint32_t)(row * 128 + q * 16));
            CP16(sb + (hl ? GA_L : GA_H) + off, &(hl ? g_Al : g_Ah)[gi]);
        }
        CPCOMMIT();
        CPWAIT();
        __syncthreads();

        int l7 = lane & 7, lg = lane >> 3;
        int bl15 = lane & 15;
#pragma unroll
        for (int ks = 0; ks < 4; ks++) {
            uint32_t ah[2][4], al[2][4];
#pragma unroll
            for (int mi = 0; mi < 2; mi++) {
                int arow = wm * 32 + mi * 16 + (lg & 1) * 8 + l7;
                uint32_t aoff = sw128((uint32_t)(arow * 128 + ks * 32 + (lg >> 1) * 16));
                ldsm_x4(ah[mi], sb + GA_H + aoff);
                ldsm_x4(al[mi], sb + GA_L + aoff);
            }
#pragma unroll
            for (int n = 0; n < 8; n++) {
                int brow = wn * 64 + n * 8 + (bl15 & 7);
                uint32_t boff = sw128((uint32_t)(brow * 128 + ks * 32 + (bl15 >> 3) * 16));
                uint32_t bh[2], bl_[2];
                ldsm_x2(bh, sb + GB_H + boff);
                ldsm_x2(bl_, sb + GB_L + boff);
#pragma unroll
                for (int mi = 0; mi < 2; mi++) {
                    mma_bf16(acc[mi][n], ah[mi], bh);
                    mma_bf16(acc[mi][n], ah[mi], bl_);
                    mma_bf16(acc[mi][n], al[mi], bh);
                }
            }
        }
    }

    int qrow = lane >> 2, qcol = 2 * (lane & 3);
#pragma unroll
    for (int mi = 0; mi < 2; mi++) {
#pragma unroll
        for (int n = 0; n < 8; n++) {
            int lcol = wn * 64 + n * 8 + qcol;
            int gc = cb + lcol;
            int gr = rb0 + wm * 32 + mi * 16 + qrow;
            float b0 = bias[lcol], b1 = bias[lcol + 1];
            size_t base0 = (size_t)gr * V + gc;
            size_t base1 = (size_t)(gr + 8) * V + gc;
            if (gc < V) {
                out[base0] = acc[mi][n][0] + b0;
                out[base1] = acc[mi][n][2] + b0;
            }
            if (gc + 1 < V) {
                out[base0 + 1] = acc[mi][n][1] + b1;
                out[base1 + 1] = acc[mi][n][3] + b1;
            }
        }
    }
}

// ---------------- launcher ----------------
extern "C" void kernel_launch(void* const* d_in, const int* in_sizes, int n_in,
                              void* d_out, int out_size) {
    const int*   ids   = (const int*)d_in[0];
    const float* embed = (const float*)d_in[1];
    const float* pos   = (const float*)d_in[2];
    const float* rW    = (const float*)d_in[3];
    const float* rb    = (const float*)d_in[4];
    const float* fcW   = (const float*)d_in[5];
    const float* fcb   = (const float*)d_in[6];
    const float* gW    = (const float*)d_in[7];
    const float* gb    = (const float*)d_in[8];
    const float* cW    = (const float*)d_in[9];
    const float* lng   = (const float*)d_in[10];
    const float* lnb   = (const float*)d_in[11];
    const float* oW    = (const float*)d_in[12];
    const float* ob    = (const float*)d_in[13];
    const int*   esrc  = (const int*)d_in[14];
    const int*   edst  = (const int*)d_in[15];
    int E = in_sizes[14];
    int V = in_sizes[12] / Dc;
    float* out = (float*)d_out;

    // ---- fork side stream: weight conversions + nxt zeroing (independent of acts) ----
    cudaEventRecord(g_evFork, 0);
    cudaStreamWaitEvent(g_s2, g_evFork, 0);
    convert_fc_kernel<<<(Nc * Dc * Dc / 8 + 255) / 256, 256, 0, g_s2>>>(fcW);
    {
        int vc = V < VMAX ? V : VMAX;
        convert_ow_kernel<<<((vc * Dc) / 8 + 255) / 256, 256, 0, g_s2>>>(oW, vc);
    }
    zero_nxt_kernel<<<(Sc * Kc * Bc * Dc) / 1024, 256, 0, g_s2>>>();
    cudaEventRecord(g_evJoin, g_s2);

    // ---- main chain (latency-bound small kernels overlap with side stream) ----
    embed_kernel<<<Sc * Bc, Dc>>>(ids, embed, pos);
    {
        dim3 rg(Sc, 4);
        router_kernel<<<rg, 256>>>(rW, rb);
    }
    topk_kernel<<<(Sc * Bc) / 4, 128>>>();
    build_groups_kernel<<<Nc, 256>>>();
    efilter_kernel<<<Sc, 256>>>(esrc, edst, E);

    // join: hop0 needs g_fch/g_fcl; edge needs zeros in g_nxt; gemm needs g_oWh/g_oWl
    cudaStreamWaitEvent(0, g_evJoin, 0);

    cudaFuncSetAttribute(hop0_mma_kernel, cudaFuncAttributeMaxDynamicSharedMemorySize, H_SMEM);
    hop0_mma_kernel<<<Nc * 16, 256, H_SMEM>>>(fcb, gW, gb);

    cudaFuncSetAttribute(edge_mma_kernel, cudaFuncAttributeMaxDynamicSharedMemorySize, E_SMEM);
    edge_mma_kernel<<<1480, 256, E_SMEM>>>(cW, fcb, gW, gb, edst);

    combine_kernel<<<Sc * Bc, Dc>>>(lng, lnb);

    cudaFuncSetAttribute(gemm_mma_kernel, cudaFuncAttributeMaxDynamicSharedMemorySize, G_SMEM);
    dim3 g(2, (V + 127) / 128);
    gemm_mma_kernel<<<g, 256, G_SMEM>>>(ob, out, V);
}